// round 5
// baseline (speedup 1.0000x reference)
#include <cuda_runtime.h>
#include <cstdint>

// AdaptiveEdgeSparsifier: per-row (4096 elems) exact k-th-largest threshold,
// then out = (adj >= kth) ? adj : 0.
//
// Algorithm: map each float to an order-preserving uint32 key, then do a
// 32-step MSB-first bitwise descent: at each step, block-count how many keys
// are >= candidate threshold; keep the bit iff count >= k. The final value is
// exactly the k-th largest key (ties handled identically to the reference's
// `adj >= kth_val`). All data stays in registers (16 keys/thread); the only
// shared state is an 8-entry per-warp partial-count array, double-buffered so
// each iteration needs a single __syncthreads.

#define N_COLS 4096
#define TPB    256

__device__ __forceinline__ unsigned f2key(float f) {
    unsigned u = __float_as_uint(f);
    // non-negative: flip sign bit; negative: flip all bits. Monotone increasing.
    return u ^ ((unsigned)((int)u >> 31) | 0x80000000u);
}

__device__ __forceinline__ float key2f(unsigned k) {
    unsigned u = (k & 0x80000000u) ? (k ^ 0x80000000u) : ~k;
    return __uint_as_float(u);
}

__global__ void __launch_bounds__(TPB)
topk_sparsify_kernel(const float4* __restrict__ in,
                     float4* __restrict__ out,
                     int kth)
{
    const size_t row_f4 = (size_t)blockIdx.x * (N_COLS / 4);
    const int tid = threadIdx.x;

    // Load 16 floats per thread as 4x float4 (fully coalesced), convert to keys.
    unsigned key[16];
#pragma unroll
    for (int i = 0; i < 4; ++i) {
        float4 v = in[row_f4 + tid + i * TPB];
        key[i * 4 + 0] = f2key(v.x);
        key[i * 4 + 1] = f2key(v.y);
        key[i * 4 + 2] = f2key(v.z);
        key[i * 4 + 3] = f2key(v.w);
    }

    __shared__ int partial[2][TPB / 32];

    unsigned result = 0u;
#pragma unroll 1
    for (int bit = 31; bit >= 0; --bit) {
        const unsigned t = result | (1u << bit);

        // Per-thread count of keys >= t over 16 register-resident keys.
        int c = 0;
#pragma unroll
        for (int i = 0; i < 16; ++i) c += (key[i] >= t) ? 1 : 0;

        // Warp reduce (REDUX.SUM on sm_103a), lane 0 publishes per-warp partial.
        c = __reduce_add_sync(0xFFFFFFFFu, c);
        if ((tid & 31) == 0) partial[bit & 1][tid >> 5] = c;
        __syncthreads();

        // Every thread redundantly sums the 8 partials (LDS broadcast) and
        // makes the identical decision — no second barrier needed; the parity
        // double-buffer plus next iteration's barrier protects reuse.
        int total = 0;
#pragma unroll
        for (int w = 0; w < TPB / 32; ++w) total += partial[bit & 1][w];
        if (total >= kth) result = t;
    }

    // result == k-th largest key. Emit thresholded floats (recover float from
    // key — saves 16 registers vs. keeping the original floats alive).
#pragma unroll
    for (int i = 0; i < 4; ++i) {
        float4 v;
        v.x = (key[i * 4 + 0] >= result) ? key2f(key[i * 4 + 0]) : 0.0f;
        v.y = (key[i * 4 + 1] >= result) ? key2f(key[i * 4 + 1]) : 0.0f;
        v.z = (key[i * 4 + 2] >= result) ? key2f(key[i * 4 + 2]) : 0.0f;
        v.w = (key[i * 4 + 3] >= result) ? key2f(key[i * 4 + 3]) : 0.0f;
        out[row_f4 + tid + i * TPB] = v;
    }
}

extern "C" void kernel_launch(void* const* d_in, const int* in_sizes, int n_in,
                              void* d_out, int out_size)
{
    const float4* in = (const float4*)d_in[0];
    float4* out = (float4*)d_out;

    const int rows = in_sizes[0] / N_COLS;   // 8 * 4096 = 32768 rows

    // k = max(1, int(n * (1 - SPARSITY_RATIO))) with n = 4096, ratio = 0.3
    int k = (int)((double)N_COLS * (1.0 - 0.3));  // 2867, matches Python int()
    if (k < 1) k = 1;

    topk_sparsify_kernel<<<rows, TPB>>>(in, out, k);
}

// round 6
// speedup vs baseline: 1.2796x; 1.2796x over previous
#include <cuda_runtime.h>
#include <cstdint>

// AdaptiveEdgeSparsifier: per-row (4096) exact k-th-largest threshold, then
// out = (adj >= kth) ? adj : 0.
//
// R5: bitwise MSB-first descent on order-preserving uint keys, with
//  (a) early exit when count(key >= t) == k exactly (output set already
//      determined — identical to thresholding at the true k-th value),
//  (b) after the top 8 bits, compact the still-active keys (prefix match)
//      into shared memory and let warp 0 finish the remaining bits
//      barrier-free with warp-local reductions.

#define N_COLS 4096
#define TPB    256
#define KEYS   16
#define PHASE1_END 24   // phase 1 resolves bits 31..24 with all keys in regs

__device__ __forceinline__ unsigned f2key(float f) {
    unsigned u = __float_as_uint(f);
    return u ^ ((unsigned)((int)u >> 31) | 0x80000000u);  // monotone map
}
__device__ __forceinline__ float key2f(unsigned k) {
    unsigned u = (k & 0x80000000u) ? (k ^ 0x80000000u) : ~k;
    return __uint_as_float(u);
}

__global__ void __launch_bounds__(TPB)
topk_sparsify_kernel(const float4* __restrict__ in,
                     float4* __restrict__ out,
                     int kth)
{
    const size_t row_f4 = (size_t)blockIdx.x * (N_COLS / 4);
    const int tid = threadIdx.x;

    __shared__ int      s_partial[2][TPB / 32];
    __shared__ unsigned s_keys[N_COLS];          // worst-case full row
    __shared__ int      s_nact;
    __shared__ int      s_base;
    __shared__ unsigned s_result;

    if (tid == 0) { s_nact = 0; s_base = 0; }

    // Load 16 floats/thread (coalesced float4), convert to keys.
    unsigned key[KEYS];
#pragma unroll
    for (int i = 0; i < 4; ++i) {
        float4 v = in[row_f4 + tid + i * TPB];
        key[4 * i + 0] = f2key(v.x);
        key[4 * i + 1] = f2key(v.y);
        key[4 * i + 2] = f2key(v.z);
        key[4 * i + 3] = f2key(v.w);
    }

    unsigned result = 0u;
    bool done = false;

    // ---- Phase 1: bits 31..24, block-wide counting over register keys ----
#pragma unroll 1
    for (int bit = 31; bit >= PHASE1_END; --bit) {
        const unsigned t = result | (1u << bit);
        int c = 0;
#pragma unroll
        for (int i = 0; i < KEYS; ++i) c += (key[i] >= t) ? 1 : 0;
        c = __reduce_add_sync(0xFFFFFFFFu, c);
        if ((tid & 31) == 0) s_partial[bit & 1][tid >> 5] = c;
        __syncthreads();
        int total = 0;
#pragma unroll
        for (int w = 0; w < TPB / 32; ++w) total += s_partial[bit & 1][w];
        if (total >= kth) {
            result = t;
            if (total == kth) { done = true; break; }   // set equality: finished
        }
    }

    if (!done) {
        // ---- Compact actives (prefix match: result <= key < result+2^24) ----
        // Invariant: count(>=result) >= k, count(>=result+2^24) < k, so
        // base < k and nact >= 1 always.
        const unsigned hi = result + (1u << PHASE1_END);
        int cnt_hi = 0, myact = 0;
#pragma unroll
        for (int i = 0; i < KEYS; ++i) {
            bool above  = key[i] >= hi;
            bool active = (key[i] >= result) && !above;
            cnt_hi += above ? 1 : 0;
            myact  += active ? 1 : 0;
        }
        int ofs = atomicAdd(&s_nact, myact);    // warp-aggregated by ptxas
        atomicAdd(&s_base, cnt_hi);
#pragma unroll
        for (int i = 0; i < KEYS; ++i) {
            if (key[i] >= result && key[i] < hi) s_keys[ofs++] = key[i];
        }
        __syncthreads();

        // ---- Phase 2: warp 0 finishes bits 23..0 barrier-free ----
        if (tid < 32) {
            const int nact = s_nact;
            const int base = s_base;
            unsigned r = result;
#pragma unroll 1
            for (int bit = PHASE1_END - 1; bit >= 0; --bit) {
                const unsigned t = r | (1u << bit);
                int c = 0;
                for (int i = tid; i < nact; i += 32)
                    c += (s_keys[i] >= t) ? 1 : 0;
                c = __reduce_add_sync(0xFFFFFFFFu, c);
                const int total = base + c;
                if (total >= kth) {
                    r = t;
                    if (total == kth) break;
                }
            }
            if (tid == 0) s_result = r;
        }
        __syncthreads();
        result = s_result;
    }

    // ---- Emit thresholded output ----
#pragma unroll
    for (int i = 0; i < 4; ++i) {
        float4 v;
        v.x = (key[4 * i + 0] >= result) ? key2f(key[4 * i + 0]) : 0.0f;
        v.y = (key[4 * i + 1] >= result) ? key2f(key[4 * i + 1]) : 0.0f;
        v.z = (key[4 * i + 2] >= result) ? key2f(key[4 * i + 2]) : 0.0f;
        v.w = (key[4 * i + 3] >= result) ? key2f(key[4 * i + 3]) : 0.0f;
        out[row_f4 + tid + i * TPB] = v;
    }
}

extern "C" void kernel_launch(void* const* d_in, const int* in_sizes, int n_in,
                              void* d_out, int out_size)
{
    const float4* in  = (const float4*)d_in[0];
    float4*       out = (float4*)d_out;

    const int rows = in_sizes[0] / N_COLS;   // 8 * 4096 = 32768

    int k = (int)((double)N_COLS * (1.0 - 0.3));  // 2867, matches Python int()
    if (k < 1) k = 1;

    topk_sparsify_kernel<<<rows, TPB>>>(in, out, k);
}

// round 7
// speedup vs baseline: 1.3882x; 1.0848x over previous
#include <cuda_runtime.h>
#include <cstdint>

// AdaptiveEdgeSparsifier: per-row (4096) exact k-th-largest threshold, then
// out = (adj >= kth) ? adj : 0.
//
// R6: value-space 256-bin histogram select. Bins are a monotone map
// idx = clamp(trunc(f*1024) - 410, 0, 255) covering [0.40, 0.65) — the
// +/-6-sigma window of the per-row 0.7-quantile for N(0,1) rows. Middle
// buckets hold ~1.4 elements, so after one histogram pass + a 256-bin
// suffix scan, the k-th element is found among <=32 candidates by a single
// warp in a couple of reduce_max steps. End buckets (the ~94% of clamped
// elements) are counted with predicates, never atomics. If the threshold
// ever falls outside the window or the bucket overflows (never for this
// data, but must stay correct), an exact 32-bit bitwise block descent
// fallback runs instead.

#define N_COLS 4096
#define TPB    256
#define KEYS   16
#define VOFF   410          // floor(0.40 * 1024)
#define FSCALE 1024.0f
#define MAXACT 32

__device__ __forceinline__ unsigned f2key(float f) {
    unsigned u = __float_as_uint(f);
    return u ^ ((unsigned)((int)u >> 31) | 0x80000000u);   // monotone bijection
}
__device__ __forceinline__ float key2f(unsigned k) {
    unsigned u = (k & 0x80000000u) ? (k ^ 0x80000000u) : ~k;
    return __uint_as_float(u);
}

__global__ void __launch_bounds__(TPB)
topk_sparsify_kernel(const float4* __restrict__ in,
                     float4* __restrict__ out,
                     int kth)
{
    const size_t row_f4 = (size_t)blockIdx.x * (N_COLS / 4);
    const int tid  = threadIdx.x;
    const int lane = tid & 31;

    __shared__ int      s_hist[256];
    __shared__ unsigned s_act[MAXACT];
    __shared__ int      s_part[2][TPB / 32];
    __shared__ int      s_c255, s_cur;
    __shared__ int      s_j, s_m, s_nact, s_fb;
    __shared__ float    s_ft;

    s_hist[tid] = 0;                       // TPB == 256 == bins
    if (tid == 0) { s_c255 = 0; s_cur = 0; }

    // ---- load 16 floats/thread, coalesced float4 ----
    float f[KEYS];
    {
        const float4* p = in + row_f4 + tid;
#pragma unroll
        for (int i = 0; i < 4; ++i) {
            float4 v = p[i * TPB];
            f[4 * i + 0] = v.x; f[4 * i + 1] = v.y;
            f[4 * i + 2] = v.z; f[4 * i + 3] = v.w;
        }
    }
    __syncthreads();

    // ---- pass 1: monotone value-space binning + histogram ----
    // idx(f) = clamp(trunc(f*1024) - 410, 0, 255): every step monotone
    // non-decreasing, so bucket order == value order. Buckets 1..254 go to
    // smem atomics (~1.4 hits/thread, spread addresses); bucket 255 is
    // counted by predicate (bucket 0's count is never needed).
    int idx[KEYS];
    int c255 = 0;
#pragma unroll
    for (int i = 0; i < KEYS; ++i) {
        int v = (int)(f[i] * FSCALE) - VOFF;   // cvt.rzi saturates; monotone
        int b = min(max(v, 0), 255);
        idx[i] = b;
        c255 += (b == 255) ? 1 : 0;
        if ((unsigned)(b - 1) <= 253u)
            atomicAdd(&s_hist[b], 1);
    }
    c255 = __reduce_add_sync(0xFFFFFFFFu, c255);
    if (lane == 0) atomicAdd(&s_c255, c255);
    __syncthreads();

    // ---- warp 0: suffix scan over bins, pick bucket j* containing k-th ----
    if (tid < 32) {
        int h[8];
        int lt = 0;
#pragma unroll
        for (int r = 0; r < 8; ++r) { h[r] = s_hist[tid * 8 + r]; lt += h[r]; }
        // inclusive suffix sum of lane totals
        int x = lt;
#pragma unroll
        for (int d = 1; d < 32; d <<= 1) {
            int y = __shfl_down_sync(0xFFFFFFFFu, x, d);
            if (lane + d < 32) x += y;
        }
        const int cumbase = s_c255 + x;        // count(idx >= 8*lane)
        // largest j in this lane's 8 bins with cum(j) >= k (cum nonincreasing)
        int cand = -1, candcum = 0, candh = 0, pre = 0;
#pragma unroll
        for (int r = 0; r < 8; ++r) {
            int j   = tid * 8 + r;
            int cum = cumbase - pre;           // count(idx >= j)
            if (j >= 1 && cum >= kth) { cand = j; candcum = cum; candh = h[r]; }
            pre += h[r];
        }
        int jstar = __reduce_max_sync(0xFFFFFFFFu, cand);
        if (cand == jstar && jstar >= 1) {     // unique owner lane
            int base = candcum - candh;        // count(idx >= j*+1)
            s_j = jstar; s_m = kth - base; s_nact = candh;
            s_fb = (jstar == 255) | (candh > MAXACT) | (candh <= 0);
        }
        if (lane == 0 && jstar < 1) s_fb = 1;
    }
    __syncthreads();

    float ft;
    if (!s_fb) {
        // ---- collect bucket members (<=32), select m-th largest ----
        const int js = s_j;
#pragma unroll
        for (int i = 0; i < KEYS; ++i) {
            if (idx[i] == js) {
                int pos = atomicAdd(&s_cur, 1);
                s_act[pos] = f2key(f[i]);
            }
        }
        __syncthreads();
        if (tid < 32) {
            const int nact = s_nact, m = s_m;
            unsigned kv = (lane < nact) ? s_act[lane] : 0u;
            for (int i = 1; i < m; ++i) {      // remove m-1 maxima (dup-safe)
                unsigned mx   = __reduce_max_sync(0xFFFFFFFFu, kv);
                unsigned ball = __ballot_sync(0xFFFFFFFFu, kv == mx);
                if (lane == __ffs(ball) - 1) kv = 0u;
            }
            unsigned t = __reduce_max_sync(0xFFFFFFFFu, kv);
            if (lane == 0) s_ft = key2f(t);
        }
        __syncthreads();
        ft = s_ft;
    } else {
        // ---- exact fallback: 32-bit MSB-first descent over all keys ----
        unsigned kk[KEYS];
#pragma unroll
        for (int i = 0; i < KEYS; ++i) kk[i] = f2key(f[i]);
        unsigned result = 0u;
#pragma unroll 1
        for (int bit = 31; bit >= 0; --bit) {
            const unsigned t = result | (1u << bit);
            int c = 0;
#pragma unroll
            for (int i = 0; i < KEYS; ++i) c += (kk[i] >= t) ? 1 : 0;
            c = __reduce_add_sync(0xFFFFFFFFu, c);
            if (lane == 0) s_part[bit & 1][tid >> 5] = c;
            __syncthreads();
            int tot = 0;
#pragma unroll
            for (int w = 0; w < TPB / 32; ++w) tot += s_part[bit & 1][w];
            if (tot >= kth) { result = t; if (tot == kth) break; }  // uniform
        }
        ft = key2f(result);
    }

    // ---- output: fp-domain threshold (FSETP/FSEL, fma pipe) ----
    {
        float4* q = out + row_f4 + tid;
#pragma unroll
        for (int i = 0; i < 4; ++i) {
            float4 v;
            v.x = (f[4 * i + 0] >= ft) ? f[4 * i + 0] : 0.0f;
            v.y = (f[4 * i + 1] >= ft) ? f[4 * i + 1] : 0.0f;
            v.z = (f[4 * i + 2] >= ft) ? f[4 * i + 2] : 0.0f;
            v.w = (f[4 * i + 3] >= ft) ? f[4 * i + 3] : 0.0f;
            q[i * TPB] = v;
        }
    }
}

extern "C" void kernel_launch(void* const* d_in, const int* in_sizes, int n_in,
                              void* d_out, int out_size)
{
    const float4* in  = (const float4*)d_in[0];
    float4*       out = (float4*)d_out;

    const int rows = in_sizes[0] / N_COLS;        // 8 * 4096 = 32768

    int k = (int)((double)N_COLS * (1.0 - 0.3));  // 2867, matches Python int()
    if (k < 1) k = 1;

    topk_sparsify_kernel<<<rows, TPB>>>(in, out, k);
}

// round 8
// speedup vs baseline: 1.4908x; 1.0739x over previous
#include <cuda_runtime.h>
#include <cstdint>

// AdaptiveEdgeSparsifier: per-row (4096) exact k-th-largest threshold, then
// out = (adj >= kth) ? adj : 0.
//
// R7: value-space 256-bin histogram select (window [411/1024, 665/1024),
// covering the per-row 0.7-quantile of N(0,1) rows with ~6 sigma margin),
// now with BRANCH-FREE predicated smem reductions (@p red.shared / @p
// atom.shared in inline asm) instead of divergent `if (..) atomicAdd`
// regions, no idx[] array (bucket membership recomputed from exact float
// bounds), and a register-light exact bitwise-descent fallback (keys
// recomputed on the fly) for the never-taken out-of-window / overflow case.

#define N_COLS 4096
#define TPB    256
#define KEYS   16
#define MAXACT 32

__device__ __forceinline__ unsigned f2key(float f) {
    unsigned u = __float_as_uint(f);
    return u ^ ((unsigned)((int)u >> 31) | 0x80000000u);   // monotone bijection
}
__device__ __forceinline__ float key2f(unsigned k) {
    unsigned u = (k & 0x80000000u) ? (k ^ 0x80000000u) : ~k;
    return __uint_as_float(u);
}

__global__ void __launch_bounds__(TPB, 5)
topk_sparsify_kernel(const float4* __restrict__ in,
                     float4* __restrict__ out,
                     int kth)
{
    const size_t row_f4 = (size_t)blockIdx.x * (N_COLS / 4);
    const int tid  = threadIdx.x;
    const int lane = tid & 31;

    __shared__ int      s_hist[256];
    __shared__ unsigned s_act[MAXACT];
    __shared__ int      s_part[2][TPB / 32];
    __shared__ int      s_c255, s_cur;
    __shared__ int      s_j, s_m, s_nact, s_fb;
    __shared__ float    s_ft;

    s_hist[tid] = 0;                           // TPB == 256 == bins
    if (tid == 0) { s_c255 = 0; s_cur = 0; }

    // ---- load 16 floats/thread (coalesced float4); overlaps the barrier ----
    float f[KEYS];
    {
        const float4* p = in + row_f4 + tid;
#pragma unroll
        for (int i = 0; i < 4; ++i) {
            float4 v = p[i * TPB];
            f[4 * i + 0] = v.x; f[4 * i + 1] = v.y;
            f[4 * i + 2] = v.z; f[4 * i + 3] = v.w;
        }
    }
    __syncthreads();

    // ---- pass 1: histogram, fully predicated (no divergent regions) ----
    // bin b = (int)(f*1024) - 410; b in [1,254] goes to s_hist[b] via a
    // guarded red.shared; count(b >= 255) i.e. f >= 665/1024 via predicate.
    // f*1024 is an exact power-of-two scale, so all boundaries are exact.
    const unsigned hbase = (unsigned)__cvta_generic_to_shared(s_hist);
    const float HI_F = 665.0f / 1024.0f;
    int c255 = 0;
#pragma unroll
    for (int i = 0; i < KEYS; ++i) {
        int cvt = (int)(f[i] * 1024.0f);                  // trunc toward zero
        unsigned ub   = (unsigned)(cvt - 411);            // <254 <=> b in [1,254]
        unsigned addr = hbase + 4u * (unsigned)cvt - 1640u;  // &s_hist[cvt-410]
        asm volatile(
            "{ .reg .pred p; setp.lt.u32 p, %0, 254; @p red.shared.add.u32 [%1], 1; }"
            :: "r"(ub), "r"(addr) : "memory");
        c255 += (f[i] >= HI_F) ? 1 : 0;
    }
    c255 = __reduce_add_sync(0xFFFFFFFFu, c255);
    if (lane == 0) atomicAdd(&s_c255, c255);
    __syncthreads();

    // ---- warp 0: suffix scan over bins, pick bucket j* containing k-th ----
    if (tid < 32) {
        int h[8];
        int lt = 0;
#pragma unroll
        for (int r = 0; r < 8; ++r) { h[r] = s_hist[tid * 8 + r]; lt += h[r]; }
        int x = lt;                                        // suffix sum
#pragma unroll
        for (int d = 1; d < 32; d <<= 1) {
            int y = __shfl_down_sync(0xFFFFFFFFu, x, d);
            if (lane + d < 32) x += y;
        }
        const int cumbase = s_c255 + x;                    // count(bin >= 8*lane)
        int cand = -1, candcum = 0, candh = 0, pre = 0;
#pragma unroll
        for (int r = 0; r < 8; ++r) {
            int j   = tid * 8 + r;
            int cum = cumbase - pre;                       // count(bin >= j)
            if (j >= 1 && cum >= kth) { cand = j; candcum = cum; candh = h[r]; }
            pre += h[r];
        }
        int jstar = __reduce_max_sync(0xFFFFFFFFu, cand);
        if (cand == jstar && jstar >= 1) {                 // unique owner lane
            int base = candcum - candh;                    // count(bin >= j*+1)
            s_j = jstar; s_m = kth - base; s_nact = candh;
            s_fb = (jstar == 255) | (candh > MAXACT) | (candh <= 0);
        }
        if (lane == 0 && jstar < 1) s_fb = 1;
    }
    __syncthreads();

    float ft;
    if (!s_fb) {
        // ---- collect bucket members (<=32), branch-free predicated atomics.
        // bucket j* <=> f in [ (j*+410)/1024, (j*+411)/1024 ) — exact bounds.
        // positive floats: raw bits are order-isomorphic, store them directly.
        const int js = s_j;
        const float lo = (float)(js + 410) * (1.0f / 1024.0f);
        const float hi = lo + (1.0f / 1024.0f);
        const unsigned curaddr = (unsigned)__cvta_generic_to_shared(&s_cur);
        const unsigned actbase = (unsigned)__cvta_generic_to_shared(s_act);
#pragma unroll
        for (int i = 0; i < KEYS; ++i) {
            asm volatile(
                "{ .reg .pred p; .reg .u32 t, a;\n"
                "  setp.ge.f32 p, %0, %1;\n"
                "  setp.lt.and.f32 p, %0, %2, p;\n"
                "  @p atom.shared.add.u32 t, [%3], 1;\n"
                "  @p mad.lo.u32 a, t, 4, %4;\n"
                "  @p st.shared.b32 [a], %5;\n}"
                :: "f"(f[i]), "f"(lo), "f"(hi),
                   "r"(curaddr), "r"(actbase), "r"(__float_as_uint(f[i]))
                : "memory");
        }
        __syncthreads();

        // ---- warp 0: m-th largest among <=32 candidates (dup-safe) ----
        if (tid < 32) {
            const int nact = s_nact, m = s_m;
            unsigned kv = (lane < nact) ? s_act[lane] : 0u;
            for (int i = 1; i < m; ++i) {
                unsigned mx   = __reduce_max_sync(0xFFFFFFFFu, kv);
                unsigned ball = __ballot_sync(0xFFFFFFFFu, kv == mx);
                if (lane == (int)(__ffs(ball) - 1)) kv = 0u;
            }
            unsigned t = __reduce_max_sync(0xFFFFFFFFu, kv);
            if (lane == 0) s_ft = __uint_as_float(t);
        }
        __syncthreads();
        ft = s_ft;
    } else {
        // ---- exact fallback: 32-bit MSB-first block descent; keys recomputed
        // from f[] per iteration (never taken on this data; keeps regs low) ----
        unsigned result = 0u;
#pragma unroll 1
        for (int bit = 31; bit >= 0; --bit) {
            const unsigned t = result | (1u << bit);
            int c = 0;
#pragma unroll
            for (int i = 0; i < KEYS; ++i) c += (f2key(f[i]) >= t) ? 1 : 0;
            c = __reduce_add_sync(0xFFFFFFFFu, c);
            if (lane == 0) s_part[bit & 1][tid >> 5] = c;
            __syncthreads();
            int tot = 0;
#pragma unroll
            for (int w = 0; w < TPB / 32; ++w) tot += s_part[bit & 1][w];
            if (tot >= kth) { result = t; if (tot == kth) break; }   // uniform
        }
        ft = key2f(result);
    }

    // ---- output: fp-domain threshold (FSETP/FSEL) ----
    {
        float4* q = out + row_f4 + tid;
#pragma unroll
        for (int i = 0; i < 4; ++i) {
            float4 v;
            v.x = (f[4 * i + 0] >= ft) ? f[4 * i + 0] : 0.0f;
            v.y = (f[4 * i + 1] >= ft) ? f[4 * i + 1] : 0.0f;
            v.z = (f[4 * i + 2] >= ft) ? f[4 * i + 2] : 0.0f;
            v.w = (f[4 * i + 3] >= ft) ? f[4 * i + 3] : 0.0f;
            q[i * TPB] = v;
        }
    }
}

extern "C" void kernel_launch(void* const* d_in, const int* in_sizes, int n_in,
                              void* d_out, int out_size)
{
    const float4* in  = (const float4*)d_in[0];
    float4*       out = (float4*)d_out;

    const int rows = in_sizes[0] / N_COLS;        // 8 * 4096 = 32768

    int k = (int)((double)N_COLS * (1.0 - 0.3));  // 2867, matches Python int()
    if (k < 1) k = 1;

    topk_sparsify_kernel<<<rows, TPB>>>(in, out, k);
}

// round 9
// speedup vs baseline: 2.7210x; 1.8252x over previous
#include <cuda_runtime.h>
#include <cstdint>

// AdaptiveEdgeSparsifier: per-row (4096) exact k-th-largest threshold, then
// out = (adj >= kth) ? adj : 0.
//
// R9: the per-row threshold is the 0.30 quantile (~ -0.524), i.e. NEGATIVE —
// rounds 6-8 windowed around +0.52 and silently ran the exact fallback every
// block. Window now at f in (-0.66015625, -0.3984375] (u-bits [UA, UB)),
// +-6.3 sigma around the true quantile. Pipeline: (A) count-above + collect
// in-window raw bits (branch-free predicated smem append, capacity 4096 so
// overflow is impossible); (B) 186-bin key-domain histogram over ONLY the
// ~371 collected; (C) warp-0 suffix scan -> bucket + rank; (D) gather <=32
// bucket members, warp-0 picks the m-th largest. Exact 32-bit block descent
// remains as the never-taken correctness fallback.

#define N_COLS 4096
#define TPB    256
#define KEYS   16

// u-domain window (raw bits of negative floats):
//   u in [UA, UB)  <=>  f in (-0.66015625, -0.3984375]
// key = f2key(f) (monotone); for negatives key = ~u, so
// key-window = [KLO, KHI] with KLO = ~(UB-1), KHI = ~UA.
#define UA        0xBECC0000u
#define UB        0xBF290000u
#define KLO       0x40D70000u
#define BIN_SHIFT 15
#define NBINS     186          /* (UB-UA) >> 15 */
#define HI_STRICT (-0.3984375f)/* count(f > HI_STRICT) == count(key > KHI) */
#define MAXB      32

__device__ __forceinline__ unsigned f2key(float f) {
    unsigned u = __float_as_uint(f);
    return u ^ ((unsigned)((int)u >> 31) | 0x80000000u);   // monotone bijection
}
__device__ __forceinline__ float key2f(unsigned k) {
    unsigned u = (k & 0x80000000u) ? (k ^ 0x80000000u) : ~k;
    return __uint_as_float(u);
}

__global__ void __launch_bounds__(TPB, 5)
topk_sparsify_kernel(const float4* __restrict__ in,
                     float4* __restrict__ out,
                     int kth)
{
    const size_t row_f4 = (size_t)blockIdx.x * (N_COLS / 4);
    const int tid  = threadIdx.x;
    const int lane = tid & 31;

    __shared__ unsigned s_act[N_COLS];        // collected raw bits (cap = row)
    __shared__ int      s_hist[192];          // 186 bins + pad
    __shared__ unsigned s_bucket[MAXB];
    __shared__ int      s_part[2][TPB / 32];  // fallback partials
    __shared__ int      s_chi, s_cur, s_cur2;
    __shared__ int      s_j, s_m, s_nb, s_fb;
    __shared__ float    s_ft;

    if (tid < 192) s_hist[tid] = 0;
    if (tid == 0) { s_chi = 0; s_cur = 0; s_cur2 = 0; s_fb = 0; }

    // ---- load 16 floats/thread (coalesced float4) ----
    float f[KEYS];
    {
        const float4* p = in + row_f4 + tid;
#pragma unroll
        for (int i = 0; i < 4; ++i) {
            float4 v = p[i * TPB];
            f[4 * i + 0] = v.x; f[4 * i + 1] = v.y;
            f[4 * i + 2] = v.z; f[4 * i + 3] = v.w;
        }
    }
    __syncthreads();

    // ---- Pass A: count-above (strict) + branch-free collect of in-window ----
    {
        const unsigned curaddr = (unsigned)__cvta_generic_to_shared(&s_cur);
        const unsigned actbase = (unsigned)__cvta_generic_to_shared(s_act);
        const unsigned negUA   = 0u - UA;
        const unsigned win     = UB - UA;
        int chi = 0;
#pragma unroll
        for (int i = 0; i < KEYS; ++i) {
            chi += (f[i] > HI_STRICT) ? 1 : 0;
            unsigned u = __float_as_uint(f[i]);
            asm volatile(
                "{ .reg .pred p; .reg .u32 d, t, a;\n"
                "  add.u32 d, %0, %1;\n"              // d = u - UA
                "  setp.lt.u32 p, d, %2;\n"           // u in [UA, UB)
                "  @p atom.shared.add.u32 t, [%3], 1;\n"
                "  @p mad.lo.u32 a, t, 4, %4;\n"
                "  @p st.shared.b32 [a], %0;\n}"
                :: "r"(u), "r"(negUA), "r"(win), "r"(curaddr), "r"(actbase)
                : "memory");
        }
        chi = __reduce_add_sync(0xFFFFFFFFu, chi);
        if (lane == 0) atomicAdd(&s_chi, chi);
    }
    __syncthreads();

    const int ncoll = s_cur;
    const int chi   = s_chi;

    // ---- Pass B: histogram the collected (~371) into 186 key-domain bins ----
    // bin = ((UB-1) - u) >> 15  ==  (key - KLO) >> 15, monotone increasing in f.
    for (int i = tid; i < ncoll; i += TPB) {
        unsigned u = s_act[i];
        atomicAdd(&s_hist[(UB - 1u - u) >> BIN_SHIFT], 1);
    }
    __syncthreads();

    // ---- Pass C: warp-0 suffix scan; bucket j* with cum(j*)>=k>cum(j*+1) ----
    if (tid < 32) {
        int h[6];
        int lt = 0;
#pragma unroll
        for (int r = 0; r < 6; ++r) { h[r] = s_hist[lane * 6 + r]; lt += h[r]; }
        int x = lt;                                    // suffix sum over lanes
#pragma unroll
        for (int d = 1; d < 32; d <<= 1) {
            int y = __shfl_down_sync(0xFFFFFFFFu, x, d);
            if (lane + d < 32) x += y;
        }
        const int cumbase = chi + x;                   // count(bin >= 6*lane)
        int cand = -1, candcum = 0, candh = 0, pre = 0;
#pragma unroll
        for (int r = 0; r < 6; ++r) {
            int j   = lane * 6 + r;
            int cum = cumbase - pre;                   // count(bin >= j)
            if (cum >= kth) { cand = j; candcum = cum; candh = h[r]; }
            pre += h[r];
        }
        int jstar = __reduce_max_sync(0xFFFFFFFFu, cand);
        if (cand == jstar && jstar >= 0) {             // unique owner lane
            s_j = jstar;
            s_m = kth - (candcum - candh);             // rank within bucket
            s_nb = candh;
            if (candh > MAXB) s_fb = 1;
        }
        if (lane == 0 && (jstar < 0 || chi >= kth)) s_fb = 1;
    }
    __syncthreads();

    float ft;
    if (!s_fb) {
        // ---- Pass D: gather bucket members (<= 32) as keys ----
        // bucket j*: (ubhi - u) < 0x8000, ubhi = UB-1 - (j* << 15)
        const unsigned ubhi = UB - 1u - ((unsigned)s_j << BIN_SHIFT);
        for (int i = tid; i < ncoll; i += TPB) {
            unsigned u = s_act[i];
            if ((ubhi - u) < (1u << BIN_SHIFT)) {
                int pos = atomicAdd(&s_cur2, 1);
                s_bucket[pos] = ~u;                    // key (negative floats)
            }
        }
        __syncthreads();

        // ---- warp 0: m-th largest among <=32 keys (dup-safe) ----
        if (tid < 32) {
            const int nb = s_nb, m = s_m;
            unsigned kv = (lane < nb) ? s_bucket[lane] : 0u;
            for (int i = 1; i < m; ++i) {
                unsigned mx   = __reduce_max_sync(0xFFFFFFFFu, kv);
                unsigned ball = __ballot_sync(0xFFFFFFFFu, kv == mx);
                if (lane == (int)(__ffs(ball) - 1)) kv = 0u;
            }
            unsigned t = __reduce_max_sync(0xFFFFFFFFu, kv);
            if (lane == 0) s_ft = key2f(t);
        }
        __syncthreads();
        ft = s_ft;
    } else {
        // ---- exact fallback: 32-bit MSB-first block descent (never taken) ----
        unsigned result = 0u;
#pragma unroll 1
        for (int bit = 31; bit >= 0; --bit) {
            const unsigned t = result | (1u << bit);
            int c = 0;
#pragma unroll
            for (int i = 0; i < KEYS; ++i) c += (f2key(f[i]) >= t) ? 1 : 0;
            c = __reduce_add_sync(0xFFFFFFFFu, c);
            if (lane == 0) s_part[bit & 1][tid >> 5] = c;
            __syncthreads();
            int tot = 0;
#pragma unroll
            for (int w = 0; w < TPB / 32; ++w) tot += s_part[bit & 1][w];
            if (tot >= kth) { result = t; if (tot == kth) break; }   // uniform
        }
        ft = key2f(result);
    }

    // ---- output: fp-domain threshold ----
    {
        float4* q = out + row_f4 + tid;
#pragma unroll
        for (int i = 0; i < 4; ++i) {
            float4 v;
            v.x = (f[4 * i + 0] >= ft) ? f[4 * i + 0] : 0.0f;
            v.y = (f[4 * i + 1] >= ft) ? f[4 * i + 1] : 0.0f;
            v.z = (f[4 * i + 2] >= ft) ? f[4 * i + 2] : 0.0f;
            v.w = (f[4 * i + 3] >= ft) ? f[4 * i + 3] : 0.0f;
            q[i * TPB] = v;
        }
    }
}

extern "C" void kernel_launch(void* const* d_in, const int* in_sizes, int n_in,
                              void* d_out, int out_size)
{
    const float4* in  = (const float4*)d_in[0];
    float4*       out = (float4*)d_out;

    const int rows = in_sizes[0] / N_COLS;        // 8 * 4096 = 32768

    int k = (int)((double)N_COLS * (1.0 - 0.3));  // 2867, matches Python int()
    if (k < 1) k = 1;

    topk_sparsify_kernel<<<rows, TPB>>>(in, out, k);
}

// round 10
// speedup vs baseline: 3.4607x; 1.2718x over previous
#include <cuda_runtime.h>
#include <cstdint>

// AdaptiveEdgeSparsifier: per-row (4096) exact k-th-largest threshold, then
// out = (adj >= kth) ? adj : 0.
//
// R10: same select pipeline as R9 (u-window (-0.66015625, -0.3984375] around
// the 0.30-quantile, collect -> 186-bin key histogram -> bucket -> m-th
// largest), but the row now lives in SMEM end-to-end:
//   * cp.async.bulk (TMA) GMEM->SMEM load, mbarrier completion
//   * all passes read via LDS.128; no f[16] in registers (regs ~48 -> ~28,
//     occupancy 5 -> 8 CTAs/SM)
//   * output thresholded in-place in SMEM, then one cp.async.bulk SMEM->GMEM
//     bulk-group store (no per-thread STG).
// Exact 32-bit block descent (reading SMEM) remains the never-taken fallback.

#define N_COLS    4096
#define TPB       256
#define ROW_BYTES (N_COLS * 4)
#define MAXCOLL   1024
#define MAXB      32

// u-domain window (raw bits of negative floats): u in [UA,UB) <=> f in
// (-0.66015625, -0.3984375]. For negatives key = ~u; bin = (UB-1-u)>>15.
#define UA        0xBECC0000u
#define UB        0xBF290000u
#define BIN_SHIFT 15
#define HI_STRICT (-0.3984375f)   /* count(f > HI_STRICT) == count above window */

__device__ __forceinline__ unsigned f2key(float f) {
    unsigned u = __float_as_uint(f);
    return u ^ ((unsigned)((int)u >> 31) | 0x80000000u);
}
__device__ __forceinline__ float key2f(unsigned k) {
    unsigned u = (k & 0x80000000u) ? (k ^ 0x80000000u) : ~k;
    return __uint_as_float(u);
}

// Branch-free: count-above + capacity-guarded predicated append of in-window
// raw bits to s_act.
__device__ __forceinline__ void passA_elem(float fv, int& chi,
                                           unsigned curaddr, unsigned actbase)
{
    chi += (fv > HI_STRICT) ? 1 : 0;
    unsigned u = __float_as_uint(fv);
    asm volatile(
        "{ .reg .pred p, q; .reg .u32 d, t, a;\n"
        "  add.u32 d, %0, %1;\n"                    // d = u - UA
        "  setp.lt.u32 p, d, %2;\n"                 // in window?
        "  @p atom.shared.add.u32 t, [%3], 1;\n"
        "  setp.lt.and.u32 q, t, %5, p;\n"          // slot < cap (t garbage ok)
        "  @q mad.lo.u32 a, t, 4, %4;\n"
        "  @q st.shared.b32 [a], %0;\n}"
        :: "r"(u), "r"(0u - UA), "r"(UB - UA),
           "r"(curaddr), "r"(actbase), "r"((unsigned)MAXCOLL)
        : "memory");
}

__global__ void __launch_bounds__(TPB, 8)
topk_sparsify_kernel(const float* __restrict__ in,
                     float* __restrict__ out,
                     int kth)
{
    __shared__ __align__(16) float s_row[N_COLS];        // 16 KB
    __shared__ unsigned s_act[MAXCOLL];                  // 4 KB
    __shared__ int      s_hist[192];
    __shared__ unsigned s_bucket[MAXB];
    __shared__ int      s_part[2][TPB / 32];
    __shared__ __align__(8) unsigned long long s_mbar;
    __shared__ int      s_chi, s_cur, s_cur2, s_j, s_m, s_nb, s_fb;
    __shared__ float    s_ft;

    const int tid  = threadIdx.x;
    const int lane = tid & 31;
    const unsigned rowaddr = (unsigned)__cvta_generic_to_shared(s_row);
    const unsigned mbar    = (unsigned)__cvta_generic_to_shared(&s_mbar);

    if (tid < 192) s_hist[tid] = 0;
    if (tid == 0) {
        s_chi = 0; s_cur = 0; s_cur2 = 0; s_fb = 0;
        asm volatile("mbarrier.init.shared.b64 [%0], 1;" :: "r"(mbar) : "memory");
    }
    __syncthreads();

    // ---- async bulk load: GMEM row -> SMEM (one thread) ----
    if (tid == 0) {
        asm volatile("mbarrier.arrive.expect_tx.shared.b64 _, [%0], %1;"
                     :: "r"(mbar), "r"((unsigned)ROW_BYTES) : "memory");
        const float* src = in + (size_t)blockIdx.x * N_COLS;
        asm volatile(
            "cp.async.bulk.shared::cta.global.mbarrier::complete_tx::bytes "
            "[%0], [%1], %2, [%3];"
            :: "r"(rowaddr), "l"(src), "r"((unsigned)ROW_BYTES), "r"(mbar)
            : "memory");
    }
    // all threads wait for the tile (parity 0)
    asm volatile(
        "{ .reg .pred P;\n"
        "W%=: mbarrier.try_wait.parity.acquire.cta.shared::cta.b64 P, [%0], 0;\n"
        "  @!P bra W%=;\n}"
        :: "r"(mbar) : "memory");

    // ---- Pass A: count-above + collect in-window (from SMEM, LDS.128) ----
    const float4* sr = (const float4*)s_row;
    {
        const unsigned curaddr = (unsigned)__cvta_generic_to_shared(&s_cur);
        const unsigned actbase = (unsigned)__cvta_generic_to_shared(s_act);
        int chi = 0;
#pragma unroll
        for (int i = 0; i < 4; ++i) {
            float4 v = sr[i * TPB + tid];
            passA_elem(v.x, chi, curaddr, actbase);
            passA_elem(v.y, chi, curaddr, actbase);
            passA_elem(v.z, chi, curaddr, actbase);
            passA_elem(v.w, chi, curaddr, actbase);
        }
        chi = __reduce_add_sync(0xFFFFFFFFu, chi);
        if (lane == 0) atomicAdd(&s_chi, chi);
    }
    __syncthreads();

    const int ncoll = s_cur;
    const int chi   = s_chi;
    const int nscan = (ncoll < MAXCOLL) ? ncoll : MAXCOLL;
    if (tid == 0 && ncoll > MAXCOLL) s_fb = 1;   // collect overflow -> fallback

    // ---- Pass B: histogram the collected (~371) into 186 key-domain bins ----
    for (int i = tid; i < nscan; i += TPB) {
        unsigned u = s_act[i];
        atomicAdd(&s_hist[(UB - 1u - u) >> BIN_SHIFT], 1);
    }
    __syncthreads();

    // ---- Pass C: warp-0 suffix scan; bucket j* with cum(j*)>=k>cum(j*+1) ----
    if (tid < 32) {
        int h[6];
        int lt = 0;
#pragma unroll
        for (int r = 0; r < 6; ++r) { h[r] = s_hist[lane * 6 + r]; lt += h[r]; }
        int x = lt;                                    // suffix sum over lanes
#pragma unroll
        for (int d = 1; d < 32; d <<= 1) {
            int y = __shfl_down_sync(0xFFFFFFFFu, x, d);
            if (lane + d < 32) x += y;
        }
        const int cumbase = chi + x;                   // count(bin >= 6*lane)
        int cand = -1, candcum = 0, candh = 0, pre = 0;
#pragma unroll
        for (int r = 0; r < 6; ++r) {
            int j   = lane * 6 + r;
            int cum = cumbase - pre;                   // count(bin >= j)
            if (cum >= kth) { cand = j; candcum = cum; candh = h[r]; }
            pre += h[r];
        }
        int jstar = __reduce_max_sync(0xFFFFFFFFu, cand);
        if (cand == jstar && jstar >= 0) {             // unique owner lane
            s_j = jstar;
            s_m = kth - (candcum - candh);
            s_nb = candh;
            if (candh > MAXB) s_fb = 1;
        }
        if (lane == 0 && (jstar < 0 || chi >= kth)) s_fb = 1;
    }
    __syncthreads();

    float ft;
    if (!s_fb) {
        // ---- Pass D: gather bucket members (<= 32) as keys ----
        const unsigned ubhi = UB - 1u - ((unsigned)s_j << BIN_SHIFT);
        for (int i = tid; i < nscan; i += TPB) {
            unsigned u = s_act[i];
            if ((ubhi - u) < (1u << BIN_SHIFT)) {
                int pos = atomicAdd(&s_cur2, 1);
                s_bucket[pos] = ~u;                    // key of negative float
            }
        }
        __syncthreads();

        // warp 0: m-th largest among <=32 keys (dup-safe)
        if (tid < 32) {
            const int nb = s_nb, m = s_m;
            unsigned kv = (lane < nb) ? s_bucket[lane] : 0u;
            for (int i = 1; i < m; ++i) {
                unsigned mx   = __reduce_max_sync(0xFFFFFFFFu, kv);
                unsigned ball = __ballot_sync(0xFFFFFFFFu, kv == mx);
                if (lane == (int)(__ffs(ball) - 1)) kv = 0u;
            }
            unsigned t = __reduce_max_sync(0xFFFFFFFFu, kv);
            if (lane == 0) s_ft = key2f(t);
        }
        __syncthreads();
        ft = s_ft;
    } else {
        // ---- exact fallback: 32-bit MSB-first descent over SMEM row ----
        unsigned result = 0u;
#pragma unroll 1
        for (int bit = 31; bit >= 0; --bit) {
            const unsigned t = result | (1u << bit);
            int c = 0;
#pragma unroll
            for (int i = 0; i < 4; ++i) {
                float4 v = sr[i * TPB + tid];
                c += (f2key(v.x) >= t) ? 1 : 0;
                c += (f2key(v.y) >= t) ? 1 : 0;
                c += (f2key(v.z) >= t) ? 1 : 0;
                c += (f2key(v.w) >= t) ? 1 : 0;
            }
            c = __reduce_add_sync(0xFFFFFFFFu, c);
            if (lane == 0) s_part[bit & 1][tid >> 5] = c;
            __syncthreads();
            int tot = 0;
#pragma unroll
            for (int w = 0; w < TPB / 32; ++w) tot += s_part[bit & 1][w];
            if (tot >= kth) { result = t; if (tot == kth) break; }   // uniform
        }
        ft = key2f(result);
    }

    // ---- threshold row in-place in SMEM, then async bulk store ----
    float4* srw = (float4*)s_row;
#pragma unroll
    for (int i = 0; i < 4; ++i) {
        float4 v = srw[i * TPB + tid];
        v.x = (v.x >= ft) ? v.x : 0.0f;
        v.y = (v.y >= ft) ? v.y : 0.0f;
        v.z = (v.z >= ft) ? v.z : 0.0f;
        v.w = (v.w >= ft) ? v.w : 0.0f;
        srw[i * TPB + tid] = v;
    }
    asm volatile("fence.proxy.async.shared::cta;" ::: "memory");
    __syncthreads();

    if (tid == 0) {
        float* dst = out + (size_t)blockIdx.x * N_COLS;
        asm volatile(
            "cp.async.bulk.global.shared::cta.bulk_group [%0], [%1], %2;"
            :: "l"(dst), "r"(rowaddr), "r"((unsigned)ROW_BYTES) : "memory");
        asm volatile("cp.async.bulk.commit_group;" ::: "memory");
        asm volatile("cp.async.bulk.wait_group 0;" ::: "memory");
    }
}

extern "C" void kernel_launch(void* const* d_in, const int* in_sizes, int n_in,
                              void* d_out, int out_size)
{
    const float* in  = (const float*)d_in[0];
    float*       out = (float*)d_out;

    const int rows = in_sizes[0] / N_COLS;        // 8 * 4096 = 32768

    int k = (int)((double)N_COLS * (1.0 - 0.3));  // 2867, matches Python int()
    if (k < 1) k = 1;

    topk_sparsify_kernel<<<rows, TPB>>>(in, out, k);
}